// round 6
// baseline (speedup 1.0000x reference)
#include <cuda_runtime.h>
#include <math.h>

#define B_    64
#define LS    256
#define LW    256
#define MM    16
#define NSTEP 10
#define HH    1024
#define DD    1280
#define BM    (B_*MM)                      /* 1024 */
#define S_ENTRIES (B_*(NSTEP+1)*LS)        /* 180224: real-part floats */
#define RHO_OFF   S_ENTRIES                /* rho region starts here */

// -------- scratch ----------------------------------------------------------
__device__ float g_xs[BM*512];          // [w_r | w_i] rows, [1024,512]
__device__ float g_S[11u*BM*HH];        // static preact per step (10 W1 + 1 V1)
__device__ float g_yp[11*MM*HH];        // y-part + bias, per (step, m)
__device__ float g_dyn[2*B_*HH];        // [sr|si]@W1dyn , [sr|si]@V1dyn
__device__ float g_h[BM*HH];            // relu hidden for eta path
__device__ float g_rho[BM];
__device__ float g_g[B_*HH];            // sum_m rho*h
__device__ float g_phi[B_*LS];
__device__ float g_srsi[B_*2*LS];       // [cos | sin] per batch row, [64,512]
__device__ float g_part[8*B_*LS];       // split-K partials for eta_net

// ---------------------------------------------------------------------------
// P0: build xs from w_M_real/w_M_imag (transpose (0,2,1)), copy phi
__global__ void k_prep(const float* __restrict__ phi,
                       const float* __restrict__ wr,
                       const float* __restrict__ wi)
{
    int idx = blockIdx.x*256 + threadIdx.x;
    if (idx < BM*512) {
        int bm = idx >> 9, k = idx & 511;
        int b = bm >> 4, m = bm & 15;
        float v;
        if (k < 256) v = wr[((size_t)b*LW + k)*MM + m];
        else         v = wi[((size_t)b*LW + (k-256))*MM + m];
        g_xs[idx] = v;
    }
    if (idx < B_*LS) g_phi[idx] = phi[idx];
}

// P2: yp[z][m][h] = sum_l y[l,m] * W[z][1024+l][h] + bias   (z=10 -> V1/c1)
__global__ void k_yp(const float* __restrict__ y,  const float* __restrict__ W1,
                     const float* __restrict__ V1, const float* __restrict__ b1,
                     const float* __restrict__ c1)
{
    int h = blockIdx.x*256 + threadIdx.x;
    int m = blockIdx.y;
    int z = blockIdx.z;
    const float* Wy = (z < 10) ? (W1 + (size_t)z*DD*HH + (size_t)1024*HH)
                               : (V1 + (size_t)1024*HH);
    float bias = (z < 10) ? b1[z*HH + h] : c1[h];
    __shared__ float ys[256];
    ys[threadIdx.x] = y[(size_t)threadIdx.x*MM + m];
    __syncthreads();
    float acc = bias;
    #pragma unroll 4
    for (int l = 0; l < 256; l++) acc += ys[l] * Wy[(size_t)l*HH + h];
    g_yp[((size_t)z*MM + m)*HH + h] = acc;
}

// P1: S[z] = xs[1024,512] @ W[z][512:1024,:]   (128x128x8 register-tiled sgemm)
__global__ __launch_bounds__(256) void k_static(const float* __restrict__ W1,
                                                const float* __restrict__ V1)
{
    int z = blockIdx.z;
    const float* Bmat = (z < 10) ? (W1 + (size_t)z*DD*HH + (size_t)512*HH)
                                 : (V1 + (size_t)512*HH);
    float* C = g_S + (size_t)z*BM*HH;
    const float* A = g_xs;
    const int lda = 512, ldb = HH, ldc = HH, K = 512;

    __shared__ float As[8][128];
    __shared__ float Bs[8][128];
    int tid = threadIdx.x;
    int tx = tid & 15, ty = tid >> 4;
    float acc[8][8];
    #pragma unroll
    for (int i = 0; i < 8; i++)
        #pragma unroll
        for (int j = 0; j < 8; j++) acc[i][j] = 0.f;

    int arow = tid >> 1, acol = (tid & 1) << 2;
    int brow = tid >> 5, bcol = (tid & 31) << 2;
    const float* Ap = A + (size_t)(blockIdx.y*128 + arow)*lda + acol;
    const float* Bp = Bmat + (size_t)brow*ldb + blockIdx.x*128 + bcol;

    for (int k0 = 0; k0 < K; k0 += 8) {
        float4 av = *(const float4*)(Ap + k0);
        As[acol+0][arow] = av.x; As[acol+1][arow] = av.y;
        As[acol+2][arow] = av.z; As[acol+3][arow] = av.w;
        float4 bv = *(const float4*)(Bp + (size_t)k0*ldb);
        *(float4*)(&Bs[brow][bcol]) = bv;
        __syncthreads();
        #pragma unroll
        for (int k = 0; k < 8; k++) {
            float a[8], bb[8];
            #pragma unroll
            for (int i = 0; i < 8; i++) a[i]  = As[k][ty*8+i];
            #pragma unroll
            for (int j = 0; j < 8; j++) bb[j] = Bs[k][tx*8+j];
            #pragma unroll
            for (int i = 0; i < 8; i++)
                #pragma unroll
                for (int j = 0; j < 8; j++) acc[i][j] += a[i]*bb[j];
        }
        __syncthreads();
    }
    int crow0 = blockIdx.y*128 + ty*8;
    int ccol0 = blockIdx.x*128 + tx*8;
    #pragma unroll
    for (int i = 0; i < 8; i++) {
        *(float4*)(&C[(size_t)(crow0+i)*ldc + ccol0]) =
            make_float4(acc[i][0], acc[i][1], acc[i][2], acc[i][3]);
        *(float4*)(&C[(size_t)(crow0+i)*ldc + ccol0 + 4]) =
            make_float4(acc[i][4], acc[i][5], acc[i][6], acc[i][7]);
    }
}

// K1: s = cis(phi). Output carries ONLY the real part (complex64 -> float32
// cast semantics): out[b][n][l] = cos(phi). sin kept in g_srsi for compute.
__global__ void k_s(float* __restrict__ out, int n)
{
    int b = blockIdx.x, l = threadIdx.x;
    float p = g_phi[b*LS + l];
    float sn, cs;
    sincosf(p, &sn, &cs);
    g_srsi[b*2*LS + l]      = cs;
    g_srsi[b*2*LS + LS + l] = sn;
    out[((size_t)b*(NSTEP+1) + n)*LS + l] = cs;   // real plane only
}

// K2: dyn[z] = srsi[64,512] @ (z? V1 : W1[n]) rows 0..511 -> [64,1024]
__global__ __launch_bounds__(256) void k_dyn(const float* __restrict__ W1,
                                             const float* __restrict__ V1, int n)
{
    int z = blockIdx.z;
    const float* Bmat = (z == 0) ? (W1 + (size_t)n*DD*HH) : V1;
    float* C = g_dyn + (size_t)z*B_*HH;
    const float* A = g_srsi;     // [64,512]
    int col0 = blockIdx.x*64;

    __shared__ float As[8][64];
    __shared__ float Bs[8][64];
    int tid = threadIdx.x;
    int tx = tid & 15, ty = tid >> 4;
    float acc[4][4];
    #pragma unroll
    for (int i = 0; i < 4; i++)
        #pragma unroll
        for (int j = 0; j < 4; j++) acc[i][j] = 0.f;

    int arow = tid >> 2, acol = (tid & 3) << 1;   // 64 rows x 8k, float2
    int brow = tid >> 5, bcol = (tid & 31) << 1;  // 8k x 64 cols, float2

    for (int k0 = 0; k0 < 512; k0 += 8) {
        float2 av = *(const float2*)(A + (size_t)arow*512 + k0 + acol);
        As[acol][arow] = av.x; As[acol+1][arow] = av.y;
        float2 bv = *(const float2*)(Bmat + (size_t)(k0+brow)*HH + col0 + bcol);
        Bs[brow][bcol] = bv.x; Bs[brow][bcol+1] = bv.y;
        __syncthreads();
        #pragma unroll
        for (int k = 0; k < 8; k++) {
            float a[4], bb[4];
            #pragma unroll
            for (int i = 0; i < 4; i++) a[i]  = As[k][ty*4+i];
            #pragma unroll
            for (int j = 0; j < 4; j++) bb[j] = Bs[k][tx*4+j];
            #pragma unroll
            for (int i = 0; i < 4; i++)
                #pragma unroll
                for (int j = 0; j < 4; j++) acc[i][j] += a[i]*bb[j];
        }
        __syncthreads();
    }
    #pragma unroll
    for (int i = 0; i < 4; i++)
        #pragma unroll
        for (int j = 0; j < 4; j++)
            C[(size_t)(ty*4+i)*HH + col0 + tx*4 + j] = acc[i][j];
}

// K3: h = relu(dyn1 + S1 + yp1); rho = sigmoid(sum relu(dynV+SV+ypV)*V2 + c2)
// rho written [B][N][M] at float offset RHO_OFF (=180224).
__global__ void k_hrho(const float* __restrict__ V2, const float* __restrict__ c2,
                       float* __restrict__ out, int n)
{
    int bm = blockIdx.x, b = bm >> 4, m = bm & 15;
    const float* S1 = g_S + (size_t)n*BM*HH  + (size_t)bm*HH;
    const float* SV = g_S + (size_t)10*BM*HH + (size_t)bm*HH;
    const float* y1 = g_yp + ((size_t)n*MM  + m)*HH;
    const float* yV = g_yp + ((size_t)10*MM + m)*HH;
    const float* d1 = g_dyn + (size_t)b*HH;
    const float* dV = g_dyn + (size_t)B_*HH + (size_t)b*HH;
    float* hrow = g_h + (size_t)bm*HH;

    float acc = 0.f;
    for (int j = threadIdx.x; j < HH; j += 256) {
        float hv  = fmaxf(d1[j] + S1[j] + y1[j], 0.f);
        hrow[j] = hv;
        float hrv = fmaxf(dV[j] + SV[j] + yV[j], 0.f);
        acc += hrv * V2[j];
    }
    #pragma unroll
    for (int off = 16; off; off >>= 1)
        acc += __shfl_down_sync(0xffffffffu, acc, off);
    __shared__ float red[8];
    if ((threadIdx.x & 31) == 0) red[threadIdx.x >> 5] = acc;
    __syncthreads();
    if (threadIdx.x == 0) {
        float t = 0.f;
        #pragma unroll
        for (int i = 0; i < 8; i++) t += red[i];
        float r = 1.f/(1.f + expf(-(t + c2[0])));
        g_rho[bm] = r;
        out[RHO_OFF + ((size_t)b*NSTEP + n)*MM + m] = r;
    }
}

// K4a: g[b,h] = sum_m rho[b,m] * h[b,m,h]
__global__ void k_g()
{
    int h = blockIdx.x*256 + threadIdx.x;
    int b = blockIdx.y;
    float acc = 0.f;
    #pragma unroll
    for (int m = 0; m < 16; m++)
        acc += g_rho[b*16+m] * g_h[((size_t)(b*16+m))*HH + h];
    g_g[(size_t)b*HH + h] = acc;
}

// K4b1: split-K partials of eta_net = g[64,1024] @ W2[n][1024,256]
__global__ __launch_bounds__(256) void k_etap(const float* __restrict__ W2, int n)
{
    const float* A = g_g;                        // [64,1024]
    const float* Bmat = W2 + (size_t)n*HH*LS;    // [1024,256]
    int ks = blockIdx.y;                         // 8 K slices of 128
    int col0 = blockIdx.x*64;                    // 4 col tiles
    float* C = g_part + (size_t)ks*B_*LS;

    __shared__ float As[8][64];
    __shared__ float Bs[8][64];
    int tid = threadIdx.x;
    int tx = tid & 15, ty = tid >> 4;
    float acc[4][4];
    #pragma unroll
    for (int i = 0; i < 4; i++)
        #pragma unroll
        for (int j = 0; j < 4; j++) acc[i][j] = 0.f;

    int arow = tid >> 2, acol = (tid & 3) << 1;
    int brow = tid >> 5, bcol = (tid & 31) << 1;
    int kbeg = ks*128, kend = kbeg + 128;

    for (int k0 = kbeg; k0 < kend; k0 += 8) {
        float2 av = *(const float2*)(A + (size_t)arow*HH + k0 + acol);
        As[acol][arow] = av.x; As[acol+1][arow] = av.y;
        float2 bv = *(const float2*)(Bmat + (size_t)(k0+brow)*LS + col0 + bcol);
        Bs[brow][bcol] = bv.x; Bs[brow][bcol+1] = bv.y;
        __syncthreads();
        #pragma unroll
        for (int k = 0; k < 8; k++) {
            float a[4], bb[4];
            #pragma unroll
            for (int i = 0; i < 4; i++) a[i]  = As[k][ty*4+i];
            #pragma unroll
            for (int j = 0; j < 4; j++) bb[j] = Bs[k][tx*4+j];
            #pragma unroll
            for (int i = 0; i < 4; i++)
                #pragma unroll
                for (int j = 0; j < 4; j++) acc[i][j] += a[i]*bb[j];
        }
        __syncthreads();
    }
    #pragma unroll
    for (int i = 0; i < 4; i++)
        #pragma unroll
        for (int j = 0; j < 4; j++)
            C[(size_t)(ty*4+i)*LS + col0 + tx*4 + j] = acc[i][j];
}

// K4b2: phi -= sum_ks partial + (sum_m rho)*b2[n]
__global__ void k_update(const float* __restrict__ b2, int n)
{
    int idx = blockIdx.x*256 + threadIdx.x;   // 16384 = 64*256
    int b = idx >> 8, l = idx & 255;
    float e = 0.f;
    #pragma unroll
    for (int ks = 0; ks < 8; ks++) e += g_part[(size_t)ks*B_*LS + idx];
    float rs = 0.f;
    #pragma unroll
    for (int m = 0; m < 16; m++) rs += g_rho[b*16+m];
    e += rs * b2[(size_t)n*LS + l];
    g_phi[idx] -= e;
}

// ---------------------------------------------------------------------------
extern "C" void kernel_launch(void* const* d_in, const int* in_sizes, int n_in,
                              void* d_out, int out_size)
{
    // Identify inputs by element count (robust to either metadata ordering).
    const float *phi=0,*wr=0,*wi=0,*y=0,*W1=0,*b1=0,*W2=0,*b2=0,
                *V1=0,*c1=0,*V2=0,*c2=0;
    bool insertion = (n_in > 0 && in_sizes[0] == 16384);
    int seen262144 = 0, seen1024 = 0;
    for (int i = 0; i < n_in; i++) {
        const float* p = (const float*)d_in[i];
        switch (in_sizes[i]) {
            case 16384:    phi = p; break;
            case 4096:     y   = p; break;
            case 13107200: W1  = p; break;
            case 10240:    b1  = p; break;
            case 2621440:  W2  = p; break;
            case 2560:     b2  = p; break;
            case 1310720:  V1  = p; break;
            case 1:        c2  = p; break;
            case 262144:
                if (seen262144++ == 0) { if (insertion) wr = p; else wi = p; }
                else                   { if (insertion) wi = p; else wr = p; }
                break;
            case 1024:
                if (seen1024++ == 0)   { if (insertion) c1 = p; else V2 = p; }
                else                   { if (insertion) V2 = p; else c1 = p; }
                break;
            default: break;
        }
    }
    float* out = (float*)d_out;

    k_prep  <<<2048, 256>>>(phi, wr, wi);
    k_yp    <<<dim3(4,16,11), 256>>>(y, W1, V1, b1, c1);
    k_static<<<dim3(8,8,11), 256>>>(W1, V1);

    for (int n = 0; n < NSTEP; n++) {
        k_s     <<<64, 256>>>(out, n);
        k_dyn   <<<dim3(16,1,2), 256>>>(W1, V1, n);
        k_hrho  <<<1024, 256>>>(V2, c2, out, n);
        k_g     <<<dim3(4,64), 256>>>();
        k_etap  <<<dim3(4,8), 256>>>(W2, n);
        k_update<<<64, 256>>>(b2, n);
    }
    k_s<<<64, 256>>>(out, NSTEP);   // s_final real part into slot 10
}

// round 7
// speedup vs baseline: 1.0305x; 1.0305x over previous
#include <cuda_runtime.h>
#include <math.h>

#define B_    64
#define LS    256
#define LW    256
#define MM    16
#define NSTEP 10
#define HH    1024
#define DD    1280
#define BM    (B_*MM)                      /* 1024 */
#define S_ENTRIES (B_*(NSTEP+1)*LS)        /* 180224: real-part floats */
#define RHO_OFF   S_ENTRIES                /* rho region starts here */

// -------- scratch ----------------------------------------------------------
__device__ float g_xs[BM*512];          // [w_r | w_i] rows, [1024,512]
__device__ float g_S[11u*BM*HH];        // static preact per step (10 W1 + 1 V1)
__device__ float g_yp[11*MM*HH];        // y-part + bias, per (step, m)
__device__ float g_dyn[2*B_*HH];        // [sr|si]@W1dyn , [sr|si]@V1dyn
__device__ float g_rho[BM];
__device__ float g_g[B_*HH];            // sum_m rho*h (atomic accumulated)
__device__ float g_phi[B_*LS];
__device__ float g_srsi[B_*2*LS];       // [cos | sin] per batch row, [64,512]
__device__ float g_part[8*B_*LS];       // split-K partials for eta_net

// ---------------------------------------------------------------------------
// P0: build xs (transpose (0,2,1)); phi copy + initial sincos + out slot 0
__global__ void k_prep(const float* __restrict__ phi,
                       const float* __restrict__ wr,
                       const float* __restrict__ wi,
                       float* __restrict__ out)
{
    int idx = blockIdx.x*256 + threadIdx.x;
    if (idx < BM*512) {
        int bm = idx >> 9, k = idx & 511;
        int b = bm >> 4, m = bm & 15;
        float v;
        if (k < 256) v = wr[((size_t)b*LW + k)*MM + m];
        else         v = wi[((size_t)b*LW + (k-256))*MM + m];
        g_xs[idx] = v;
    }
    if (idx < B_*LS) {
        float p = phi[idx];
        g_phi[idx] = p;
        float sn, cs;
        sincosf(p, &sn, &cs);
        int b = idx >> 8, l = idx & 255;
        g_srsi[b*2*LS + l]      = cs;
        g_srsi[b*2*LS + LS + l] = sn;
        out[((size_t)b*(NSTEP+1) + 0)*LS + l] = cs;
    }
}

// P2: yp[z][m][h] = sum_l y[l,m]*W[z][1024+l][h] + bias. grid (4,11), m inside.
__global__ __launch_bounds__(256) void k_yp(
    const float* __restrict__ y,  const float* __restrict__ W1,
    const float* __restrict__ V1, const float* __restrict__ b1,
    const float* __restrict__ c1)
{
    int h = blockIdx.x*256 + threadIdx.x;
    int z = blockIdx.y;
    const float* Wy = (z < 10) ? (W1 + (size_t)z*DD*HH + (size_t)1024*HH)
                               : (V1 + (size_t)1024*HH);
    float bias = (z < 10) ? b1[z*HH + h] : c1[h];

    __shared__ float ys[256][16];
    for (int t = threadIdx.x; t < 256*16; t += 256)
        ys[t >> 4][t & 15] = y[t];
    __syncthreads();

    float acc[16];
    #pragma unroll
    for (int m = 0; m < 16; m++) acc[m] = bias;
    for (int l = 0; l < 256; l++) {
        float wv = Wy[(size_t)l*HH + h];
        #pragma unroll
        for (int m = 0; m < 16; m++) acc[m] += ys[l][m] * wv;
    }
    #pragma unroll
    for (int m = 0; m < 16; m++)
        g_yp[((size_t)z*MM + m)*HH + h] = acc[m];
}

// P1: S[z] = xs[1024,512] @ W[z][512:1024,:]  (128x128x8, double-buffered)
__global__ __launch_bounds__(256) void k_static(const float* __restrict__ W1,
                                                const float* __restrict__ V1)
{
    int z = blockIdx.z;
    const float* Bmat = (z < 10) ? (W1 + (size_t)z*DD*HH + (size_t)512*HH)
                                 : (V1 + (size_t)512*HH);
    float* C = g_S + (size_t)z*BM*HH;
    const float* A = g_xs;
    const int lda = 512, ldb = HH, ldc = HH;
    const int NCH = 64;   // 512 / 8

    __shared__ float As[2][8][128];
    __shared__ float Bs[2][8][128];
    int tid = threadIdx.x;
    int tx = tid & 15, ty = tid >> 4;
    float acc[8][8];
    #pragma unroll
    for (int i = 0; i < 8; i++)
        #pragma unroll
        for (int j = 0; j < 8; j++) acc[i][j] = 0.f;

    int arow = tid >> 1, acol = (tid & 1) << 2;
    int brow = tid >> 5, bcol = (tid & 31) << 2;
    const float* Ap = A + (size_t)(blockIdx.y*128 + arow)*lda + acol;
    const float* Bp = Bmat + (size_t)brow*ldb + blockIdx.x*128 + bcol;

    // preload chunk 0
    {
        float4 av = *(const float4*)(Ap);
        As[0][acol+0][arow] = av.x; As[0][acol+1][arow] = av.y;
        As[0][acol+2][arow] = av.z; As[0][acol+3][arow] = av.w;
        float4 bv = *(const float4*)(Bp);
        *(float4*)(&Bs[0][brow][bcol]) = bv;
    }
    __syncthreads();

    for (int kc = 0; kc < NCH; kc++) {
        int cur = kc & 1;
        float4 av, bv;
        if (kc + 1 < NCH) {
            av = *(const float4*)(Ap + (kc+1)*8);
            bv = *(const float4*)(Bp + (size_t)(kc+1)*8*ldb);
        }
        #pragma unroll
        for (int k = 0; k < 8; k++) {
            float a[8], bb[8];
            #pragma unroll
            for (int i = 0; i < 8; i++) a[i]  = As[cur][k][ty*8+i];
            #pragma unroll
            for (int j = 0; j < 8; j++) bb[j] = Bs[cur][k][tx*8+j];
            #pragma unroll
            for (int i = 0; i < 8; i++)
                #pragma unroll
                for (int j = 0; j < 8; j++) acc[i][j] += a[i]*bb[j];
        }
        if (kc + 1 < NCH) {
            int nxt = cur ^ 1;
            As[nxt][acol+0][arow] = av.x; As[nxt][acol+1][arow] = av.y;
            As[nxt][acol+2][arow] = av.z; As[nxt][acol+3][arow] = av.w;
            *(float4*)(&Bs[nxt][brow][bcol]) = bv;
        }
        __syncthreads();
    }

    int crow0 = blockIdx.y*128 + ty*8;
    int ccol0 = blockIdx.x*128 + tx*8;
    #pragma unroll
    for (int i = 0; i < 8; i++) {
        *(float4*)(&C[(size_t)(crow0+i)*ldc + ccol0]) =
            make_float4(acc[i][0], acc[i][1], acc[i][2], acc[i][3]);
        *(float4*)(&C[(size_t)(crow0+i)*ldc + ccol0 + 4]) =
            make_float4(acc[i][4], acc[i][5], acc[i][6], acc[i][7]);
    }
}

// K2: dyn[z] = srsi[64,512] @ (z? V1 : W1[n]) rows 0..511 -> [64,1024]
// Also zeroes g_g for this step (blocks with z==0).
__global__ __launch_bounds__(256) void k_dyn(const float* __restrict__ W1,
                                             const float* __restrict__ V1, int n)
{
    if (blockIdx.z == 0) {
        int t = blockIdx.x*256 + threadIdx.x;   // 4096 threads
        #pragma unroll
        for (int i = 0; i < 16; i++) g_g[t + i*4096] = 0.f;
    }

    int z = blockIdx.z;
    const float* Bmat = (z == 0) ? (W1 + (size_t)n*DD*HH) : V1;
    float* C = g_dyn + (size_t)z*B_*HH;
    const float* A = g_srsi;     // [64,512]
    int col0 = blockIdx.x*64;

    __shared__ float As[8][64];
    __shared__ float Bs[8][64];
    int tid = threadIdx.x;
    int tx = tid & 15, ty = tid >> 4;
    float acc[4][4];
    #pragma unroll
    for (int i = 0; i < 4; i++)
        #pragma unroll
        for (int j = 0; j < 4; j++) acc[i][j] = 0.f;

    int arow = tid >> 2, acol = (tid & 3) << 1;
    int brow = tid >> 5, bcol = (tid & 31) << 1;

    for (int k0 = 0; k0 < 512; k0 += 8) {
        float2 av = *(const float2*)(A + (size_t)arow*512 + k0 + acol);
        As[acol][arow] = av.x; As[acol+1][arow] = av.y;
        float2 bv = *(const float2*)(Bmat + (size_t)(k0+brow)*HH + col0 + bcol);
        Bs[brow][bcol] = bv.x; Bs[brow][bcol+1] = bv.y;
        __syncthreads();
        #pragma unroll
        for (int k = 0; k < 8; k++) {
            float a[4], bb[4];
            #pragma unroll
            for (int i = 0; i < 4; i++) a[i]  = As[k][ty*4+i];
            #pragma unroll
            for (int j = 0; j < 4; j++) bb[j] = Bs[k][tx*4+j];
            #pragma unroll
            for (int i = 0; i < 4; i++)
                #pragma unroll
                for (int j = 0; j < 4; j++) acc[i][j] += a[i]*bb[j];
        }
        __syncthreads();
    }
    #pragma unroll
    for (int i = 0; i < 4; i++)
        #pragma unroll
        for (int j = 0; j < 4; j++)
            C[(size_t)(ty*4+i)*HH + col0 + tx*4 + j] = acc[i][j];
}

// K3: h = relu(dyn1+S1+yp1) kept in regs; rho = sigmoid(<relu(dynV+SV+ypV),V2>+c2)
// Accumulates rho*h into g_g via atomics (replaces k_g); writes rho to out.
__global__ void k_hrho(const float* __restrict__ V2, const float* __restrict__ c2,
                       float* __restrict__ out, int n)
{
    int bm = blockIdx.x, b = bm >> 4, m = bm & 15;
    const float* S1 = g_S + (size_t)n*BM*HH  + (size_t)bm*HH;
    const float* SV = g_S + (size_t)10*BM*HH + (size_t)bm*HH;
    const float* y1 = g_yp + ((size_t)n*MM  + m)*HH;
    const float* yV = g_yp + ((size_t)10*MM + m)*HH;
    const float* d1 = g_dyn + (size_t)b*HH;
    const float* dV = g_dyn + (size_t)B_*HH + (size_t)b*HH;

    float hv[4];
    float acc = 0.f;
    #pragma unroll
    for (int jj = 0; jj < 4; jj++) {
        int j = threadIdx.x + jj*256;
        hv[jj] = fmaxf(d1[j] + S1[j] + y1[j], 0.f);
        float hrv = fmaxf(dV[j] + SV[j] + yV[j], 0.f);
        acc += hrv * V2[j];
    }
    #pragma unroll
    for (int off = 16; off; off >>= 1)
        acc += __shfl_down_sync(0xffffffffu, acc, off);
    __shared__ float red[8];
    __shared__ float s_r;
    if ((threadIdx.x & 31) == 0) red[threadIdx.x >> 5] = acc;
    __syncthreads();
    if (threadIdx.x == 0) {
        float t = 0.f;
        #pragma unroll
        for (int i = 0; i < 8; i++) t += red[i];
        float r = 1.f/(1.f + expf(-(t + c2[0])));
        s_r = r;
        g_rho[bm] = r;
        out[RHO_OFF + ((size_t)b*NSTEP + n)*MM + m] = r;
    }
    __syncthreads();
    float r = s_r;
    #pragma unroll
    for (int jj = 0; jj < 4; jj++)
        atomicAdd(&g_g[(size_t)b*HH + threadIdx.x + jj*256], r * hv[jj]);
}

// K4b1: split-K partials of eta_net = g[64,1024] @ W2[n][1024,256]
__global__ __launch_bounds__(256) void k_etap(const float* __restrict__ W2, int n)
{
    const float* A = g_g;                        // [64,1024]
    const float* Bmat = W2 + (size_t)n*HH*LS;    // [1024,256]
    int ks = blockIdx.y;
    int col0 = blockIdx.x*64;
    float* C = g_part + (size_t)ks*B_*LS;

    __shared__ float As[8][64];
    __shared__ float Bs[8][64];
    int tid = threadIdx.x;
    int tx = tid & 15, ty = tid >> 4;
    float acc[4][4];
    #pragma unroll
    for (int i = 0; i < 4; i++)
        #pragma unroll
        for (int j = 0; j < 4; j++) acc[i][j] = 0.f;

    int arow = tid >> 2, acol = (tid & 3) << 1;
    int brow = tid >> 5, bcol = (tid & 31) << 1;
    int kbeg = ks*128, kend = kbeg + 128;

    for (int k0 = kbeg; k0 < kend; k0 += 8) {
        float2 av = *(const float2*)(A + (size_t)arow*HH + k0 + acol);
        As[acol][arow] = av.x; As[acol+1][arow] = av.y;
        float2 bv = *(const float2*)(Bmat + (size_t)(k0+brow)*LS + col0 + bcol);
        Bs[brow][bcol] = bv.x; Bs[brow][bcol+1] = bv.y;
        __syncthreads();
        #pragma unroll
        for (int k = 0; k < 8; k++) {
            float a[4], bb[4];
            #pragma unroll
            for (int i = 0; i < 4; i++) a[i]  = As[k][ty*4+i];
            #pragma unroll
            for (int j = 0; j < 4; j++) bb[j] = Bs[k][tx*4+j];
            #pragma unroll
            for (int i = 0; i < 4; i++)
                #pragma unroll
                for (int j = 0; j < 4; j++) acc[i][j] += a[i]*bb[j];
        }
        __syncthreads();
    }
    #pragma unroll
    for (int i = 0; i < 4; i++)
        #pragma unroll
        for (int j = 0; j < 4; j++)
            C[(size_t)(ty*4+i)*LS + col0 + tx*4 + j] = acc[i][j];
}

// K4b2: phi -= eta; then s = cis(phi) -> srsi + out slot n+1 (fused k_s)
__global__ void k_update(const float* __restrict__ b2, float* __restrict__ out,
                         int n)
{
    int idx = blockIdx.x*256 + threadIdx.x;   // 16384
    int b = idx >> 8, l = idx & 255;
    float e = 0.f;
    #pragma unroll
    for (int ks = 0; ks < 8; ks++) e += g_part[(size_t)ks*B_*LS + idx];
    float rs = 0.f;
    #pragma unroll
    for (int m = 0; m < 16; m++) rs += g_rho[b*16+m];
    e += rs * b2[(size_t)n*LS + l];
    float p = g_phi[idx] - e;
    g_phi[idx] = p;

    float sn, cs;
    sincosf(p, &sn, &cs);
    g_srsi[b*2*LS + l]      = cs;
    g_srsi[b*2*LS + LS + l] = sn;
    out[((size_t)b*(NSTEP+1) + (n+1))*LS + l] = cs;
}

// ---------------------------------------------------------------------------
extern "C" void kernel_launch(void* const* d_in, const int* in_sizes, int n_in,
                              void* d_out, int out_size)
{
    const float *phi=0,*wr=0,*wi=0,*y=0,*W1=0,*b1=0,*W2=0,*b2=0,
                *V1=0,*c1=0,*V2=0,*c2=0;
    bool insertion = (n_in > 0 && in_sizes[0] == 16384);
    int seen262144 = 0, seen1024 = 0;
    for (int i = 0; i < n_in; i++) {
        const float* p = (const float*)d_in[i];
        switch (in_sizes[i]) {
            case 16384:    phi = p; break;
            case 4096:     y   = p; break;
            case 13107200: W1  = p; break;
            case 10240:    b1  = p; break;
            case 2621440:  W2  = p; break;
            case 2560:     b2  = p; break;
            case 1310720:  V1  = p; break;
            case 1:        c2  = p; break;
            case 262144:
                if (seen262144++ == 0) { if (insertion) wr = p; else wi = p; }
                else                   { if (insertion) wi = p; else wr = p; }
                break;
            case 1024:
                if (seen1024++ == 0)   { if (insertion) c1 = p; else V2 = p; }
                else                   { if (insertion) V2 = p; else c1 = p; }
                break;
            default: break;
        }
    }
    float* out = (float*)d_out;

    k_prep  <<<2048, 256>>>(phi, wr, wi, out);
    k_yp    <<<dim3(4,11), 256>>>(y, W1, V1, b1, c1);
    k_static<<<dim3(8,8,11), 256>>>(W1, V1);

    for (int n = 0; n < NSTEP; n++) {
        k_dyn   <<<dim3(16,1,2), 256>>>(W1, V1, n);
        k_hrho  <<<1024, 256>>>(V2, c2, out, n);
        k_etap  <<<dim3(4,8), 256>>>(W2, n);
        k_update<<<64, 256>>>(b2, out, n);
    }
}

// round 8
// speedup vs baseline: 1.7508x; 1.6989x over previous
#include <cuda_runtime.h>
#include <math.h>

#define B_    64
#define LS    256
#define LW    256
#define MM    16
#define NSTEP 10
#define HH    1024
#define DD    1280
#define BM    (B_*MM)                      /* 1024 */
#define S_ENTRIES (B_*(NSTEP+1)*LS)        /* 180224: real-part floats */
#define RHO_OFF   S_ENTRIES                /* rho region starts here */

// -------- scratch ----------------------------------------------------------
__device__ float g_xs[BM*512];          // [w_r | w_i] rows, [1024,512]
__device__ float g_S[11u*BM*HH];        // static preact per step (10 W1 + 1 V1)
__device__ float g_yp[11*MM*HH];        // y-part + bias, per (step, m)
__device__ float g_dyn[2*B_*HH];        // atomic: [sr|si]@W1dyn , [sr|si]@V1dyn
__device__ float g_rho[BM];
__device__ float g_g[B_*HH];            // atomic: sum_m rho*h
__device__ float g_eta[B_*LS];          // atomic: eta_net partials
__device__ float g_phi[B_*LS];
__device__ float g_srsi[B_*2*LS];       // [cos | sin] per batch row, [64,512]

// ---------------------------------------------------------------------------
// P0: build xs; phi copy + initial sincos + out slot 0; zero g_dyn for step 0
__global__ void k_prep(const float* __restrict__ phi,
                       const float* __restrict__ wr,
                       const float* __restrict__ wi,
                       float* __restrict__ out)
{
    int idx = blockIdx.x*256 + threadIdx.x;
    if (idx < BM*512) {
        int bm = idx >> 9, k = idx & 511;
        int b = bm >> 4, m = bm & 15;
        float v;
        if (k < 256) v = wr[((size_t)b*LW + k)*MM + m];
        else         v = wi[((size_t)b*LW + (k-256))*MM + m];
        g_xs[idx] = v;
    }
    if (idx < 2*B_*HH) g_dyn[idx] = 0.f;
    if (idx < B_*LS) {
        float p = phi[idx];
        g_phi[idx] = p;
        float sn, cs;
        sincosf(p, &sn, &cs);
        int b = idx >> 8, l = idx & 255;
        g_srsi[b*2*LS + l]      = cs;
        g_srsi[b*2*LS + LS + l] = sn;
        out[((size_t)b*(NSTEP+1) + 0)*LS + l] = cs;
    }
}

// P2: yp[z][m][h] = sum_l y[l,m]*W[z][1024+l][h] + bias. grid (4,11), m inside.
__global__ __launch_bounds__(256) void k_yp(
    const float* __restrict__ y,  const float* __restrict__ W1,
    const float* __restrict__ V1, const float* __restrict__ b1,
    const float* __restrict__ c1)
{
    int h = blockIdx.x*256 + threadIdx.x;
    int z = blockIdx.y;
    const float* Wy = (z < 10) ? (W1 + (size_t)z*DD*HH + (size_t)1024*HH)
                               : (V1 + (size_t)1024*HH);
    float bias = (z < 10) ? b1[z*HH + h] : c1[h];

    __shared__ float ys[256][16];
    for (int t = threadIdx.x; t < 256*16; t += 256)
        ys[t >> 4][t & 15] = y[t];
    __syncthreads();

    float acc[16];
    #pragma unroll
    for (int m = 0; m < 16; m++) acc[m] = bias;
    for (int l = 0; l < 256; l++) {
        float wv = Wy[(size_t)l*HH + h];
        #pragma unroll
        for (int m = 0; m < 16; m++) acc[m] += ys[l][m] * wv;
    }
    #pragma unroll
    for (int m = 0; m < 16; m++)
        g_yp[((size_t)z*MM + m)*HH + h] = acc[m];
}

// P1: S[z] = xs[1024,512] @ W[z][512:1024,:]  (128x128x8, double-buffered)
__global__ __launch_bounds__(256) void k_static(const float* __restrict__ W1,
                                                const float* __restrict__ V1)
{
    int z = blockIdx.z;
    const float* Bmat = (z < 10) ? (W1 + (size_t)z*DD*HH + (size_t)512*HH)
                                 : (V1 + (size_t)512*HH);
    float* C = g_S + (size_t)z*BM*HH;
    const float* A = g_xs;
    const int lda = 512, ldb = HH, ldc = HH;
    const int NCH = 64;

    __shared__ float As[2][8][128];
    __shared__ float Bs[2][8][128];
    int tid = threadIdx.x;
    int tx = tid & 15, ty = tid >> 4;
    float acc[8][8];
    #pragma unroll
    for (int i = 0; i < 8; i++)
        #pragma unroll
        for (int j = 0; j < 8; j++) acc[i][j] = 0.f;

    int arow = tid >> 1, acol = (tid & 1) << 2;
    int brow = tid >> 5, bcol = (tid & 31) << 2;
    const float* Ap = A + (size_t)(blockIdx.y*128 + arow)*lda + acol;
    const float* Bp = Bmat + (size_t)brow*ldb + blockIdx.x*128 + bcol;

    {
        float4 av = *(const float4*)(Ap);
        As[0][acol+0][arow] = av.x; As[0][acol+1][arow] = av.y;
        As[0][acol+2][arow] = av.z; As[0][acol+3][arow] = av.w;
        float4 bv = *(const float4*)(Bp);
        *(float4*)(&Bs[0][brow][bcol]) = bv;
    }
    __syncthreads();

    for (int kc = 0; kc < NCH; kc++) {
        int cur = kc & 1;
        float4 av, bv;
        if (kc + 1 < NCH) {
            av = *(const float4*)(Ap + (kc+1)*8);
            bv = *(const float4*)(Bp + (size_t)(kc+1)*8*ldb);
        }
        #pragma unroll
        for (int k = 0; k < 8; k++) {
            float a[8], bb[8];
            #pragma unroll
            for (int i = 0; i < 8; i++) a[i]  = As[cur][k][ty*8+i];
            #pragma unroll
            for (int j = 0; j < 8; j++) bb[j] = Bs[cur][k][tx*8+j];
            #pragma unroll
            for (int i = 0; i < 8; i++)
                #pragma unroll
                for (int j = 0; j < 8; j++) acc[i][j] += a[i]*bb[j];
        }
        if (kc + 1 < NCH) {
            int nxt = cur ^ 1;
            As[nxt][acol+0][arow] = av.x; As[nxt][acol+1][arow] = av.y;
            As[nxt][acol+2][arow] = av.z; As[nxt][acol+3][arow] = av.w;
            *(float4*)(&Bs[nxt][brow][bcol]) = bv;
        }
        __syncthreads();
    }

    int crow0 = blockIdx.y*128 + ty*8;
    int ccol0 = blockIdx.x*128 + tx*8;
    #pragma unroll
    for (int i = 0; i < 8; i++) {
        *(float4*)(&C[(size_t)(crow0+i)*ldc + ccol0]) =
            make_float4(acc[i][0], acc[i][1], acc[i][2], acc[i][3]);
        *(float4*)(&C[(size_t)(crow0+i)*ldc + ccol0 + 4]) =
            make_float4(acc[i][4], acc[i][5], acc[i][6], acc[i][7]);
    }
}

// K2: split-K dyn GEMM. grid (16 col-tiles, 4 K-slices, 2 z) = 128 blocks.
// atomicAdd into g_dyn (pre-zeroed). Blocks (ks==0,z==0) zero g_g and g_eta.
__global__ __launch_bounds__(256) void k_dyn(const float* __restrict__ W1,
                                             const float* __restrict__ V1, int n)
{
    if (blockIdx.z == 0 && blockIdx.y == 0) {
        int t = blockIdx.x*256 + threadIdx.x;    // 4096 threads
        #pragma unroll
        for (int i = 0; i < 16; i++) g_g[t + i*4096] = 0.f;
        #pragma unroll
        for (int i = 0; i < 4; i++) g_eta[t + i*4096] = 0.f;
    }

    int z = blockIdx.z;
    const float* Bmat = (z == 0) ? (W1 + (size_t)n*DD*HH) : V1;
    float* C = g_dyn + (size_t)z*B_*HH;
    const float* A = g_srsi;     // [64,512]
    int col0 = blockIdx.x*64;
    int kbeg = blockIdx.y*128, kend = kbeg + 128;

    __shared__ float As[8][64];
    __shared__ float Bs[8][64];
    int tid = threadIdx.x;
    int tx = tid & 15, ty = tid >> 4;
    float acc[4][4];
    #pragma unroll
    for (int i = 0; i < 4; i++)
        #pragma unroll
        for (int j = 0; j < 4; j++) acc[i][j] = 0.f;

    int arow = tid >> 2, acol = (tid & 3) << 1;
    int brow = tid >> 5, bcol = (tid & 31) << 1;

    for (int k0 = kbeg; k0 < kend; k0 += 8) {
        float2 av = *(const float2*)(A + (size_t)arow*512 + k0 + acol);
        As[acol][arow] = av.x; As[acol+1][arow] = av.y;
        float2 bv = *(const float2*)(Bmat + (size_t)(k0+brow)*HH + col0 + bcol);
        Bs[brow][bcol] = bv.x; Bs[brow][bcol+1] = bv.y;
        __syncthreads();
        #pragma unroll
        for (int k = 0; k < 8; k++) {
            float a[4], bb[4];
            #pragma unroll
            for (int i = 0; i < 4; i++) a[i]  = As[k][ty*4+i];
            #pragma unroll
            for (int j = 0; j < 4; j++) bb[j] = Bs[k][tx*4+j];
            #pragma unroll
            for (int i = 0; i < 4; i++)
                #pragma unroll
                for (int j = 0; j < 4; j++) acc[i][j] += a[i]*bb[j];
        }
        __syncthreads();
    }
    #pragma unroll
    for (int i = 0; i < 4; i++)
        #pragma unroll
        for (int j = 0; j < 4; j++)
            atomicAdd(&C[(size_t)(ty*4+i)*HH + col0 + tx*4 + j], acc[i][j]);
}

// K3: h = relu(dyn1+S1+yp1) in regs; rho = sigmoid(<relu(dynV+SV+ypV),V2>+c2)
// Accumulates rho*h into g_g via atomics; writes rho to out.
__global__ void k_hrho(const float* __restrict__ V2, const float* __restrict__ c2,
                       float* __restrict__ out, int n)
{
    int bm = blockIdx.x, b = bm >> 4, m = bm & 15;
    const float* S1 = g_S + (size_t)n*BM*HH  + (size_t)bm*HH;
    const float* SV = g_S + (size_t)10*BM*HH + (size_t)bm*HH;
    const float* y1 = g_yp + ((size_t)n*MM  + m)*HH;
    const float* yV = g_yp + ((size_t)10*MM + m)*HH;
    const float* d1 = g_dyn + (size_t)b*HH;
    const float* dV = g_dyn + (size_t)B_*HH + (size_t)b*HH;

    float hv[4];
    float acc = 0.f;
    #pragma unroll
    for (int jj = 0; jj < 4; jj++) {
        int j = threadIdx.x + jj*256;
        hv[jj] = fmaxf(d1[j] + S1[j] + y1[j], 0.f);
        float hrv = fmaxf(dV[j] + SV[j] + yV[j], 0.f);
        acc += hrv * V2[j];
    }
    #pragma unroll
    for (int off = 16; off; off >>= 1)
        acc += __shfl_down_sync(0xffffffffu, acc, off);
    __shared__ float red[8];
    __shared__ float s_r;
    if ((threadIdx.x & 31) == 0) red[threadIdx.x >> 5] = acc;
    __syncthreads();
    if (threadIdx.x == 0) {
        float t = 0.f;
        #pragma unroll
        for (int i = 0; i < 8; i++) t += red[i];
        float r = 1.f/(1.f + expf(-(t + c2[0])));
        s_r = r;
        g_rho[bm] = r;
        out[RHO_OFF + ((size_t)b*NSTEP + n)*MM + m] = r;
    }
    __syncthreads();
    float r = s_r;
    #pragma unroll
    for (int jj = 0; jj < 4; jj++)
        atomicAdd(&g_g[(size_t)b*HH + threadIdx.x + jj*256], r * hv[jj]);
}

// K4: split-K eta GEMM: g[64,1024] @ W2[n][1024,256].
// grid (4 col-tiles, 16 K-slices of 64) = 64 blocks. atomicAdd into g_eta.
__global__ __launch_bounds__(256) void k_etap(const float* __restrict__ W2, int n)
{
    const float* A = g_g;                        // [64,1024]
    const float* Bmat = W2 + (size_t)n*HH*LS;    // [1024,256]
    int col0 = blockIdx.x*64;
    int kbeg = blockIdx.y*64, kend = kbeg + 64;

    __shared__ float As[8][64];
    __shared__ float Bs[8][64];
    int tid = threadIdx.x;
    int tx = tid & 15, ty = tid >> 4;
    float acc[4][4];
    #pragma unroll
    for (int i = 0; i < 4; i++)
        #pragma unroll
        for (int j = 0; j < 4; j++) acc[i][j] = 0.f;

    int arow = tid >> 2, acol = (tid & 3) << 1;
    int brow = tid >> 5, bcol = (tid & 31) << 1;

    for (int k0 = kbeg; k0 < kend; k0 += 8) {
        float2 av = *(const float2*)(A + (size_t)arow*HH + k0 + acol);
        As[acol][arow] = av.x; As[acol+1][arow] = av.y;
        float2 bv = *(const float2*)(Bmat + (size_t)(k0+brow)*LS + col0 + bcol);
        Bs[brow][bcol] = bv.x; Bs[brow][bcol+1] = bv.y;
        __syncthreads();
        #pragma unroll
        for (int k = 0; k < 8; k++) {
            float a[4], bb[4];
            #pragma unroll
            for (int i = 0; i < 4; i++) a[i]  = As[k][ty*4+i];
            #pragma unroll
            for (int j = 0; j < 4; j++) bb[j] = Bs[k][tx*4+j];
            #pragma unroll
            for (int i = 0; i < 4; i++)
                #pragma unroll
                for (int j = 0; j < 4; j++) acc[i][j] += a[i]*bb[j];
        }
        __syncthreads();
    }
    #pragma unroll
    for (int i = 0; i < 4; i++)
        #pragma unroll
        for (int j = 0; j < 4; j++)
            atomicAdd(&g_eta[(size_t)(ty*4+i)*LS + col0 + tx*4 + j], acc[i][j]);
}

// K5: phi -= g_eta + (sum_m rho)*b2[n]; s = cis(phi) -> srsi + out slot n+1.
// Also zeroes g_dyn for the NEXT step (safe: hrho already consumed it).
__global__ void k_update(const float* __restrict__ b2, float* __restrict__ out,
                         int n)
{
    int idx = blockIdx.x*256 + threadIdx.x;   // 16384
    int b = idx >> 8, l = idx & 255;
    float e = g_eta[idx];
    float rs = 0.f;
    #pragma unroll
    for (int m = 0; m < 16; m++) rs += g_rho[b*16+m];
    e += rs * b2[(size_t)n*LS + l];
    float p = g_phi[idx] - e;
    g_phi[idx] = p;

    float sn, cs;
    sincosf(p, &sn, &cs);
    g_srsi[b*2*LS + l]      = cs;
    g_srsi[b*2*LS + LS + l] = sn;
    out[((size_t)b*(NSTEP+1) + (n+1))*LS + l] = cs;

    #pragma unroll
    for (int i = 0; i < 8; i++) g_dyn[idx + i*16384] = 0.f;
}

// ---------------------------------------------------------------------------
extern "C" void kernel_launch(void* const* d_in, const int* in_sizes, int n_in,
                              void* d_out, int out_size)
{
    const float *phi=0,*wr=0,*wi=0,*y=0,*W1=0,*b1=0,*W2=0,*b2=0,
                *V1=0,*c1=0,*V2=0,*c2=0;
    bool insertion = (n_in > 0 && in_sizes[0] == 16384);
    int seen262144 = 0, seen1024 = 0;
    for (int i = 0; i < n_in; i++) {
        const float* p = (const float*)d_in[i];
        switch (in_sizes[i]) {
            case 16384:    phi = p; break;
            case 4096:     y   = p; break;
            case 13107200: W1  = p; break;
            case 10240:    b1  = p; break;
            case 2621440:  W2  = p; break;
            case 2560:     b2  = p; break;
            case 1310720:  V1  = p; break;
            case 1:        c2  = p; break;
            case 262144:
                if (seen262144++ == 0) { if (insertion) wr = p; else wi = p; }
                else                   { if (insertion) wi = p; else wr = p; }
                break;
            case 1024:
                if (seen1024++ == 0)   { if (insertion) c1 = p; else V2 = p; }
                else                   { if (insertion) V2 = p; else c1 = p; }
                break;
            default: break;
        }
    }
    float* out = (float*)d_out;

    k_prep  <<<2048, 256>>>(phi, wr, wi, out);
    k_yp    <<<dim3(4,11), 256>>>(y, W1, V1, b1, c1);
    k_static<<<dim3(8,8,11), 256>>>(W1, V1);

    for (int n = 0; n < NSTEP; n++) {
        k_dyn   <<<dim3(16,4,2), 256>>>(W1, V1, n);
        k_hrho  <<<1024, 256>>>(V2, c2, out, n);
        k_etap  <<<dim3(4,16), 256>>>(W2, n);
        k_update<<<64, 256>>>(b2, out, n);
    }
}